// round 5
// baseline (speedup 1.0000x reference)
#include <cuda_runtime.h>

// Problem constants
#define CC    512          // channels
#define BSZ   8            // batch
#define HH    128
#define WW    128
#define HWSZ  16384        // H*W
#define NTOT  131072       // B*H*W

// Scratch (device globals: runtime allocation is forbidden)
__device__ float g_qkv[(size_t)3 * CC * NTOT];   // Q,K,V stacked
__device__ float g_att[(size_t)CC * NTOT];       // attention output
__device__ float g_tmp[(size_t)CC * NTOT];       // transposed xs / oh_t

__device__ __forceinline__ unsigned f2tf32(float x) {
    unsigned r;
    asm("cvt.rna.tf32.f32 %0, %1;" : "=r"(r) : "f"(x));
    return r;
}

// ---------------------------------------------------------------------------
// HW-plane transpose: dst[plane][j][i] = src[plane][i][j]  (+ optional add in
// dst-index space). plane = b*C + c, 128x128 planes. grid (4,4,B*C), blk 32x8.
// ---------------------------------------------------------------------------
__global__ __launch_bounds__(256) void transpose_hw_kernel(
    const float* __restrict__ src, float* __restrict__ dst,
    const float* __restrict__ addsrc)
{
    __shared__ float t[32][33];
    const int i0 = blockIdx.x * 32;
    const int j0 = blockIdx.y * 32;
    const long plane = (long)blockIdx.z * HWSZ;
    const int tx = threadIdx.x, ty = threadIdx.y;

#pragma unroll
    for (int r = 0; r < 4; r++)
        t[ty + 8 * r][tx] = src[plane + (long)(i0 + ty + 8 * r) * 128 + j0 + tx];
    __syncthreads();
#pragma unroll
    for (int r = 0; r < 4; r++) {
        long o = plane + (long)(j0 + ty + 8 * r) * 128 + i0 + tx;
        float v = t[tx][ty + 8 * r];
        if (addsrc) v += addsrc[o];
        dst[o] = v;
    }
}

// ---------------------------------------------------------------------------
// TF32 tensor-core GEMM with 3-stage cp.async pipeline.
// C[m,n] = sum_k A[m,k]*B[k,n], M=512, K=512, N=131072.
// bmode 0: B xs-layout (per-b base, ldb=HWSZ)   bmode 1: B is [k*NTOT+n]
// cmode 0: C -> [z][m*NTOT+n]   cmode 1: C -> xs-layout (+= addsrc if non-null)
// fp32 bits fed to HMMA tf32 directly (HW uses top 19 bits = RZ tf32).
// ---------------------------------------------------------------------------
#define BM 128
#define BN 128
#define BK 32
#define NSLAB (CC / BK)          // 16
#define AP 36                    // A smem row pad: bank = 4*grp+qid, bijective
#define BPAD 132                 // B smem row pad: bank = 4*qid+grp, bijective
#define A_FLOATS (BM * AP)       // 4608
#define B_FLOATS (BK * BPAD)     // 4224
#define STAGE_FLOATS (A_FLOATS + B_FLOATS)   // 8832
#define GEMM_STAGES 3
#define GEMM_SMEM_BYTES (GEMM_STAGES * STAGE_FLOATS * 4)   // 105984

#define CPA16(dst, src) \
    asm volatile("cp.async.cg.shared.global [%0], [%1], 16;" \
                 :: "r"(dst), "l"(src))

__device__ __forceinline__ void stage_load(
    unsigned sbase, int stage, int slab,
    const float* __restrict__ Ag, const float* __restrict__ Bg, long ldb,
    int tid)
{
    unsigned sa = sbase + (unsigned)(stage * STAGE_FLOATS) * 4u;
    // A: 128 rows x 32 floats; 2 threads/row, 16 floats (4x16B) each
    unsigned adst = sa + (unsigned)((tid >> 1) * AP + (tid & 1) * 16) * 4u;
    const float* asrc = Ag + slab * BK;
#pragma unroll
    for (int j = 0; j < 4; j++)
        CPA16(adst + j * 16u, asrc + j * 4);
    // B: 32 rows x 128 floats; 8 threads/row, 16 floats (4x16B) each
    unsigned bdst = sa + (unsigned)(A_FLOATS + (tid >> 3) * BPAD + (tid & 7) * 16) * 4u;
    const float* bsrc = Bg + (long)slab * BK * ldb;
#pragma unroll
    for (int j = 0; j < 4; j++)
        CPA16(bdst + j * 16u, bsrc + j * 4);
}

__global__ __launch_bounds__(256, 2) void tgemm_kernel(
    const float* __restrict__ A0, const float* __restrict__ A1,
    const float* __restrict__ A2,
    const float* __restrict__ B, float* __restrict__ C,
    const float* __restrict__ addsrc, int bmode, int cmode)
{
    extern __shared__ float gsm[];
    const unsigned sbase = (unsigned)__cvta_generic_to_shared(gsm);

    const int n0 = blockIdx.x * BN;
    const int m0 = blockIdx.y * BM;
    const int z  = blockIdx.z;
    const float* A = (z == 0) ? A0 : (z == 1) ? A1 : A2;

    const int tid  = threadIdx.x;
    const int lane = tid & 31;
    const int warp = tid >> 5;
    const int grp  = lane >> 2;
    const int qid  = lane & 3;
    const int mw   = (warp >> 2) * 64;
    const int nw   = (warp & 3) * 32;

    const float* Bp;
    long ldb;
    if (bmode == 0) {
        int bb = n0 >> 14;
        Bp  = B + (((long)bb * CC) << 14) + (n0 & (HWSZ - 1));
        ldb = HWSZ;
    } else {
        Bp  = B + n0;
        ldb = NTOT;
    }
    // per-thread global bases for the staging copies
    const float* Ag = A + (long)(m0 + (tid >> 1)) * CC + (tid & 1) * 16;
    const float* Bg = Bp + (long)(tid >> 3) * ldb + (tid & 7) * 16;

    float acc[4][4][4];
#pragma unroll
    for (int mi = 0; mi < 4; mi++)
#pragma unroll
        for (int ni = 0; ni < 4; ni++)
#pragma unroll
            for (int r = 0; r < 4; r++) acc[mi][ni][r] = 0.0f;

    // prologue: stages 0,1
    stage_load(sbase, 0, 0, Ag, Bg, ldb, tid);
    asm volatile("cp.async.commit_group;");
    stage_load(sbase, 1, 1, Ag, Bg, ldb, tid);
    asm volatile("cp.async.commit_group;");

    int stage = 0;
#pragma unroll 1
    for (int slab = 0; slab < NSLAB; slab++) {
        if (slab < NSLAB - 1) asm volatile("cp.async.wait_group 1;");
        else                  asm volatile("cp.async.wait_group 0;");
        __syncthreads();

        const unsigned* Asu = (const unsigned*)(gsm + stage * STAGE_FLOATS);
        const unsigned* Bsu = Asu + A_FLOATS;

#pragma unroll
        for (int ks = 0; ks < 4; ks++) {
            const int kb = ks * 8;
            unsigned a[4][4], b[4][2];
#pragma unroll
            for (int mi = 0; mi < 4; mi++) {
                int mr = mw + mi * 16 + grp;
                a[mi][0] = Asu[mr * AP + kb + qid];
                a[mi][1] = Asu[(mr + 8) * AP + kb + qid];
                a[mi][2] = Asu[mr * AP + kb + qid + 4];
                a[mi][3] = Asu[(mr + 8) * AP + kb + qid + 4];
            }
#pragma unroll
            for (int ni = 0; ni < 4; ni++) {
                int nc = nw + ni * 8 + grp;
                b[ni][0] = Bsu[(kb + qid) * BPAD + nc];
                b[ni][1] = Bsu[(kb + qid + 4) * BPAD + nc];
            }
#pragma unroll
            for (int mi = 0; mi < 4; mi++)
#pragma unroll
                for (int ni = 0; ni < 4; ni++) {
                    asm volatile(
                        "mma.sync.aligned.m16n8k8.row.col.f32.tf32.tf32.f32 "
                        "{%0,%1,%2,%3}, {%4,%5,%6,%7}, {%8,%9}, {%0,%1,%2,%3};\n"
                        : "+f"(acc[mi][ni][0]), "+f"(acc[mi][ni][1]),
                          "+f"(acc[mi][ni][2]), "+f"(acc[mi][ni][3])
                        : "r"(a[mi][0]), "r"(a[mi][1]), "r"(a[mi][2]), "r"(a[mi][3]),
                          "r"(b[ni][0]), "r"(b[ni][1]));
                }
        }

        if (slab + 2 < NSLAB) {
            int ns = stage + 2; if (ns >= GEMM_STAGES) ns -= GEMM_STAGES;
            stage_load(sbase, ns, slab + 2, Ag, Bg, ldb, tid);
            asm volatile("cp.async.commit_group;");
        }
        if (++stage == GEMM_STAGES) stage = 0;
    }

    // epilogue
    const int cq = 2 * qid;
    if (cmode == 0) {
        float* Cp = C + (long)z * CC * NTOT + (long)m0 * NTOT + n0;
#pragma unroll
        for (int mi = 0; mi < 4; mi++) {
            int r0 = mw + mi * 16 + grp;
#pragma unroll
            for (int ni = 0; ni < 4; ni++) {
                int col = nw + ni * 8 + cq;
                *(float2*)(Cp + (long)r0 * NTOT + col) =
                    make_float2(acc[mi][ni][0], acc[mi][ni][1]);
                *(float2*)(Cp + (long)(r0 + 8) * NTOT + col) =
                    make_float2(acc[mi][ni][2], acc[mi][ni][3]);
            }
        }
    } else {
        int bb = n0 >> 14;
        long off = (((long)bb * CC + m0) << 14) + (n0 & (HWSZ - 1));
        float* Cp = C + off;
        const float* Ad = addsrc ? (addsrc + off) : nullptr;
#pragma unroll
        for (int mi = 0; mi < 4; mi++) {
            int r0 = mw + mi * 16 + grp;
#pragma unroll
            for (int ni = 0; ni < 4; ni++) {
                int col = nw + ni * 8 + cq;
                long o0 = (long)r0 * HWSZ + col;
                long o1 = (long)(r0 + 8) * HWSZ + col;
                float2 v0 = make_float2(acc[mi][ni][0], acc[mi][ni][1]);
                float2 v1 = make_float2(acc[mi][ni][2], acc[mi][ni][3]);
                if (Ad) {
                    float2 s0 = *(const float2*)(Ad + o0);
                    float2 s1 = *(const float2*)(Ad + o1);
                    v0.x += s0.x; v0.y += s0.y;
                    v1.x += s1.x; v1.y += s1.y;
                }
                *(float2*)(Cp + o0) = v0;
                *(float2*)(Cp + o1) = v1;
            }
        }
    }
}

// ---------------------------------------------------------------------------
// Tensor-core attention (unchanged from R3). Contiguous sequence required.
// ---------------------------------------------------------------------------
#define PKM 136
#define PMK 132
#define ATTN_SMEM_U32 (2 * 64 * PKM + 64 * PMK + 128 * PMK)
#define ATTN_SMEM_BYTES (ATTN_SMEM_U32 * 4)

__global__ __launch_bounds__(256) void attn_tc_kernel(
    const float* __restrict__ qkv, float* __restrict__ attout)
{
    extern __shared__ unsigned smu[];
    unsigned* Qs = smu;
    unsigned* Ks = Qs + 64 * PKM;
    unsigned* Vs = Ks + 64 * PKM;
    unsigned* Ss = Vs + 64 * PMK;

    const int tid  = threadIdx.x;
    const int lane = tid & 31;
    const int warp = tid >> 5;
    const int grp  = lane >> 2;
    const int qid  = lane & 3;

    const int fix  = blockIdx.x;
    const int head = blockIdx.y;
    const int b    = blockIdx.z;

    const long base = (long)(head * 64) * NTOT + (long)b * HWSZ + (long)fix * 128;
    const float* Qg = qkv + base;
    const float* Kg = qkv + (long)CC * NTOT + base;
    const float* Vg = qkv + 2L * CC * NTOT + base;

#pragma unroll
    for (int it = 0; it < 32; it++) {
        int idx = it * 256 + tid;
        int d = idx >> 7, s = idx & 127;
        long off = (long)d * NTOT + s;
        Qs[d * PKM + s] = f2tf32(Qg[off]);
        Ks[d * PKM + s] = f2tf32(Kg[off]);
        Vs[d * PMK + s] = f2tf32(Vg[off]);
    }
    __syncthreads();

    {
        const int mw = (warp >> 1) * 32;
        const int nw = (warp & 1) * 64;
        float acc[2][8][4];
#pragma unroll
        for (int mi = 0; mi < 2; mi++)
#pragma unroll
            for (int ni = 0; ni < 8; ni++)
#pragma unroll
                for (int r = 0; r < 4; r++) acc[mi][ni][r] = 0.0f;

#pragma unroll
        for (int ks = 0; ks < 8; ks++) {
            const int kb = ks * 8;
            unsigned a[2][4], bf[8][2];
#pragma unroll
            for (int mi = 0; mi < 2; mi++) {
                int mr = mw + mi * 16 + grp;
                a[mi][0] = Qs[(kb + qid) * PKM + mr];
                a[mi][1] = Qs[(kb + qid) * PKM + mr + 8];
                a[mi][2] = Qs[(kb + qid + 4) * PKM + mr];
                a[mi][3] = Qs[(kb + qid + 4) * PKM + mr + 8];
            }
#pragma unroll
            for (int ni = 0; ni < 8; ni++) {
                int nc = nw + ni * 8 + grp;
                bf[ni][0] = Ks[(kb + qid) * PKM + nc];
                bf[ni][1] = Ks[(kb + qid + 4) * PKM + nc];
            }
#pragma unroll
            for (int mi = 0; mi < 2; mi++)
#pragma unroll
                for (int ni = 0; ni < 8; ni++) {
                    asm volatile(
                        "mma.sync.aligned.m16n8k8.row.col.f32.tf32.tf32.f32 "
                        "{%0,%1,%2,%3}, {%4,%5,%6,%7}, {%8,%9}, {%0,%1,%2,%3};\n"
                        : "+f"(acc[mi][ni][0]), "+f"(acc[mi][ni][1]),
                          "+f"(acc[mi][ni][2]), "+f"(acc[mi][ni][3])
                        : "r"(a[mi][0]), "r"(a[mi][1]), "r"(a[mi][2]), "r"(a[mi][3]),
                          "r"(bf[ni][0]), "r"(bf[ni][1]));
                }
        }
#pragma unroll
        for (int mi = 0; mi < 2; mi++) {
            int r0 = mw + mi * 16 + grp;
#pragma unroll
            for (int ni = 0; ni < 8; ni++) {
                int col = nw + ni * 8 + 2 * qid;
                Ss[r0 * PMK + col]           = __float_as_uint(acc[mi][ni][0] * 0.125f);
                Ss[r0 * PMK + col + 1]       = __float_as_uint(acc[mi][ni][1] * 0.125f);
                Ss[(r0 + 8) * PMK + col]     = __float_as_uint(acc[mi][ni][2] * 0.125f);
                Ss[(r0 + 8) * PMK + col + 1] = __float_as_uint(acc[mi][ni][3] * 0.125f);
            }
        }
    }
    __syncthreads();

#pragma unroll
    for (int r = 0; r < 16; r++) {
        unsigned* rp = Ss + (warp + r * 8) * PMK;
        float x0 = __uint_as_float(rp[lane]);
        float x1 = __uint_as_float(rp[lane + 32]);
        float x2 = __uint_as_float(rp[lane + 64]);
        float x3 = __uint_as_float(rp[lane + 96]);
        float mx = fmaxf(fmaxf(x0, x1), fmaxf(x2, x3));
#pragma unroll
        for (int o = 16; o > 0; o >>= 1)
            mx = fmaxf(mx, __shfl_xor_sync(0xffffffffu, mx, o));
        float e0 = __expf(x0 - mx), e1 = __expf(x1 - mx);
        float e2 = __expf(x2 - mx), e3 = __expf(x3 - mx);
        float s = e0 + e1 + e2 + e3;
#pragma unroll
        for (int o = 16; o > 0; o >>= 1)
            s += __shfl_xor_sync(0xffffffffu, s, o);
        float inv = 1.0f / s;
        rp[lane]      = f2tf32(e0 * inv);
        rp[lane + 32] = f2tf32(e1 * inv);
        rp[lane + 64] = f2tf32(e2 * inv);
        rp[lane + 96] = f2tf32(e3 * inv);
    }
    __syncthreads();

    {
        const int mw = (warp >> 2) * 32;
        const int nw = (warp & 3) * 32;
        float acc[2][4][4];
#pragma unroll
        for (int mi = 0; mi < 2; mi++)
#pragma unroll
            for (int ni = 0; ni < 4; ni++)
#pragma unroll
                for (int r = 0; r < 4; r++) acc[mi][ni][r] = 0.0f;

#pragma unroll
        for (int ks = 0; ks < 16; ks++) {
            const int kb = ks * 8;
            unsigned a[2][4], bf[4][2];
#pragma unroll
            for (int mi = 0; mi < 2; mi++) {
                int dr = mw + mi * 16 + grp;
                a[mi][0] = Vs[dr * PMK + kb + qid];
                a[mi][1] = Vs[(dr + 8) * PMK + kb + qid];
                a[mi][2] = Vs[dr * PMK + kb + qid + 4];
                a[mi][3] = Vs[(dr + 8) * PMK + kb + qid + 4];
            }
#pragma unroll
            for (int ni = 0; ni < 4; ni++) {
                int ir = nw + ni * 8 + grp;
                bf[ni][0] = Ss[ir * PMK + kb + qid];
                bf[ni][1] = Ss[ir * PMK + kb + qid + 4];
            }
#pragma unroll
            for (int mi = 0; mi < 2; mi++)
#pragma unroll
                for (int ni = 0; ni < 4; ni++) {
                    asm volatile(
                        "mma.sync.aligned.m16n8k8.row.col.f32.tf32.tf32.f32 "
                        "{%0,%1,%2,%3}, {%4,%5,%6,%7}, {%8,%9}, {%0,%1,%2,%3};\n"
                        : "+f"(acc[mi][ni][0]), "+f"(acc[mi][ni][1]),
                          "+f"(acc[mi][ni][2]), "+f"(acc[mi][ni][3])
                        : "r"(a[mi][0]), "r"(a[mi][1]), "r"(a[mi][2]), "r"(a[mi][3]),
                          "r"(bf[ni][0]), "r"(bf[ni][1]));
                }
        }
        float* Os = (float*)Qs;
#pragma unroll
        for (int mi = 0; mi < 2; mi++) {
            int dr = mw + mi * 16 + grp;
#pragma unroll
            for (int ni = 0; ni < 4; ni++) {
                int ic = nw + ni * 8 + 2 * qid;
                *(float2*)&Os[dr * PKM + ic] =
                    make_float2(acc[mi][ni][0], acc[mi][ni][1]);
                *(float2*)&Os[(dr + 8) * PKM + ic] =
                    make_float2(acc[mi][ni][2], acc[mi][ni][3]);
            }
        }
    }
    __syncthreads();

    const float* Os = (const float*)Qs;
#pragma unroll
    for (int it = 0; it < 32; it++) {
        int idx = it * 256 + tid;
        int d = idx >> 7, i = idx & 127;
        attout[base + (long)d * NTOT + i] = Os[d * PKM + i];
    }
}

// ---------------------------------------------------------------------------
extern "C" void kernel_launch(void* const* d_in, const int* in_sizes, int n_in,
                              void* d_out, int out_size)
{
    const float* xs   = (const float*)d_in[0];
    const float* Wq_h = (const float*)d_in[1];
    const float* Wk_h = (const float*)d_in[2];
    const float* Wv_h = (const float*)d_in[3];
    const float* Wo_h = (const float*)d_in[4];
    const float* Wq_w = (const float*)d_in[5];
    const float* Wk_w = (const float*)d_in[6];
    const float* Wv_w = (const float*)d_in[7];
    const float* Wo_w = (const float*)d_in[8];
    float* out = (float*)d_out;

    float *qkv = nullptr, *att = nullptr, *tmp = nullptr;
    cudaGetSymbolAddress((void**)&qkv, g_qkv);
    cudaGetSymbolAddress((void**)&att, g_att);
    cudaGetSymbolAddress((void**)&tmp, g_tmp);

    cudaFuncSetAttribute(attn_tc_kernel,
                         cudaFuncAttributeMaxDynamicSharedMemorySize,
                         ATTN_SMEM_BYTES);
    cudaFuncSetAttribute(tgemm_kernel,
                         cudaFuncAttributeMaxDynamicSharedMemorySize,
                         GEMM_SMEM_BYTES);

    dim3 gproj(NTOT / BN, CC / BM, 3);
    dim3 gout (NTOT / BN, CC / BM, 1);
    dim3 gattn(128, 8, 8);
    dim3 gtr(4, 4, BSZ * CC);
    dim3 btr(32, 8);

    // ---- height branch on transposed planes (seq = h, contiguous) ----
    transpose_hw_kernel<<<gtr, btr>>>(xs, tmp, nullptr);
    tgemm_kernel<<<gproj, 256, GEMM_SMEM_BYTES>>>(Wq_h, Wk_h, Wv_h, tmp, qkv, nullptr, 0, 0);
    attn_tc_kernel<<<gattn, 256, ATTN_SMEM_BYTES>>>(qkv, att);
    tgemm_kernel<<<gout, 256, GEMM_SMEM_BYTES>>>(Wo_h, Wo_h, Wo_h, att, tmp, nullptr, 1, 1);
    transpose_hw_kernel<<<gtr, btr>>>(tmp, out, xs);

    // ---- width branch (seq = w, contiguous natively) ----
    tgemm_kernel<<<gproj, 256, GEMM_SMEM_BYTES>>>(Wq_w, Wk_w, Wv_w, xs, qkv, nullptr, 0, 0);
    attn_tc_kernel<<<gattn, 256, ATTN_SMEM_BYTES>>>(qkv, att);
    tgemm_kernel<<<gout, 256, GEMM_SMEM_BYTES>>>(Wo_w, Wo_w, Wo_w, att, out, out, 1, 1);
}